// round 10
// baseline (speedup 1.0000x reference)
#include <cuda_runtime.h>

#define NN 2048
#define EE 16384
#define DIN 1280
#define MAXDEG 64          // fixed-stride CSR slot capacity

// -------- device scratch (no allocation allowed) --------
__device__ float   g_h[NN];               // h = x_orig @ W2^T
__device__ int     g_deg[NN];             // in-degree counters
__device__ float4  g_edge[NN * MAXDEG];   // {src_bits, w, w*h_src, 0} per in-edge of dst
__device__ float2  g_self[NN];            // {self_w, self_w * h_i}

__device__ __forceinline__ void pdl_wait() {
    asm volatile("griddepcontrol.wait;" ::: "memory");
}
__device__ __forceinline__ void pdl_trigger() {
    asm volatile("griddepcontrol.launch_dependents;");
}

// ------- k_h: 1024 dot-product blocks + 512 output-zeroing blocks (overlapped) -------
__global__ void __launch_bounds__(256) k_h(const float* __restrict__ xo,
                    const float* __restrict__ W2,
                    const float* __restrict__ att_src, const float* __restrict__ att_dst,
                    float* __restrict__ out, int total4) {
    const int tid = threadIdx.x, wp = tid >> 5, lane = tid & 31;

    if (blockIdx.x >= 1024) {
        // ---- zero-stream blocks: 512 blocks x 256 threads cover 2M float4 ----
        float4 z4 = make_float4(0.f, 0.f, 0.f, 0.f);
        float4* o4 = (float4*)out;
        int g = (blockIdx.x - 1024) * 256 + tid;
        for (int i = g; i < total4; i += 512 * 256) o4[i] = z4;
        pdl_trigger();
        return;
    }

    // ---- dot-product blocks: 2 rows/block, 4 warps/row ----
    __shared__ float partial[8];
    const int row = blockIdx.x * 2 + (wp >> 2);
    const int b0 = (wp & 3) * 80;                       // 320 float4 per row / 4 warps
    const float4* xr = (const float4*)(xo + (size_t)row * DIN);
    const float4* wr = (const float4*)W2;

    float acc;
    {
        float4 a = xr[b0 + lane],      b = wr[b0 + lane];
        acc = a.x * b.x + a.y * b.y + a.z * b.z + a.w * b.w;
        a = xr[b0 + 32 + lane];        b = wr[b0 + 32 + lane];
        acc += a.x * b.x + a.y * b.y + a.z * b.z + a.w * b.w;
        if (lane < 16) {
            a = xr[b0 + 64 + lane];    b = wr[b0 + 64 + lane];
            acc += a.x * b.x + a.y * b.y + a.z * b.z + a.w * b.w;
        }
    }
#pragma unroll
    for (int off = 16; off; off >>= 1) acc += __shfl_xor_sync(0xffffffffu, acc, off);
    if (lane == 0) partial[wp] = acc;
    __syncthreads();
    if (tid < 2) {
        int r = blockIdx.x * 2 + tid;
        float h = partial[tid * 4] + partial[tid * 4 + 1]
                + partial[tid * 4 + 2] + partial[tid * 4 + 3];
        g_h[r] = h;
        g_deg[r] = 0;
        float z = (att_src[0] + att_dst[0]) * h;        // self-loop logit
        float self = z > 0.f ? z : 0.2f * z;
        float sw = __expf(self);                         // unshifted (validated)
        g_self[r] = make_float2(sw, sw * h);
    }
    pdl_trigger();
}

// ------- k_scatter: CSR scatter + per-edge exp weight (shift-free) -------
__global__ void k_scatter(const int* __restrict__ ei,
                          const float* __restrict__ att_src,
                          const float* __restrict__ att_dst) {
    pdl_wait();                                          // k_h's h/deg must be visible
    int e = blockIdx.x * blockDim.x + threadIdx.x;
    if (e < EE) {
        int s = ei[e];
        int d = ei[EE + e];
        float hs = g_h[s], hd = g_h[d];
        float z = att_src[0] * hs + att_dst[0] * hd;
        float l = z > 0.f ? z : 0.2f * z;                // leaky-relu(0.2)
        float w = __expf(l);
        int p = atomicAdd(&g_deg[d], 1);
        if (p < MAXDEG) {
            g_edge[d * MAXDEG + p] = make_float4(__int_as_float(s), w, w * hs, 0.f);
        }
    }
    pdl_trigger();
}

// GAT value for node i inside ego mask `row`
__device__ __forceinline__ float ego_e(int i, const unsigned* row, float bi) {
    float2 sf = g_self[i];
    float denom = sf.x, num = sf.y;
    int di = min(g_deg[i], MAXDEG);
    const float4* ep = g_edge + i * MAXDEG;
#pragma unroll 4
    for (int j = 0; j < di; j++) {
        float4 pk = ep[j];
        int s = __float_as_int(pk.x);
        if ((row[s >> 5] >> (s & 31)) & 1u) { denom += pk.y; num += pk.z; }
    }
    return __expf(num / denom + bi);
}

// ------- k_ego: 64-thread block per ego — mask, GAT, softmax, sparse scatter -------
__global__ void __launch_bounds__(64) k_ego(const float* __restrict__ bias,
                                            float* __restrict__ out, int write_mask) {
    __shared__ unsigned row[64];
    __shared__ float red[2];
    const int v = blockIdx.x;
    const int tid = threadIdx.x, lane = tid & 31, wp = tid >> 5;
    const float bi = bias[0];

    pdl_wait();                                          // CSR + zeros visible
    row[tid] = 0u;
    __syncthreads();

    // ---- mask build: iteration i => k=i (broadcast), j=tid; depth-2 loads ----
    const int dv = min(g_deg[v], MAXDEG);
    if (tid == 0) atomicOr(&row[v >> 5], 1u << (v & 31));
    const float* ex = (const float*)g_edge;              // .x at stride 4
    for (int k = 0; k < dv; k++) {
        int s = __float_as_int(__ldg(&ex[(v * MAXDEG + k) * 4]));
        if (tid == 0) atomicOr(&row[s >> 5], 1u << (s & 31));
        if (tid < min(g_deg[s], MAXDEG)) {
            int u = __float_as_int(__ldg(&ex[(s * MAXDEG + tid) * 4]));
            atomicOr(&row[u >> 5], 1u << (u & 31));
        }
    }
    __syncthreads();

    // ---- GAT + exp per word (thread tid owns row[tid]'s bits) ----
    float* so = out + (size_t)v * NN;
    float* mo = out + (size_t)NN * NN + (size_t)v * NN;
    float evloc[4];
    float sm = 0.f;
    {
        unsigned m = row[tid];
        int nb = 0;
        while (m) {
            int b = __ffs(m) - 1;
            m &= m - 1;
            int i = tid * 32 + b;
            float e = ego_e(i, row, bi);
            if (nb < 4) evloc[nb] = e;
            else        so[i] = e;                       // rare spill (word w/ >4 bits)
            nb++;
            sm += e;
        }
    }
#pragma unroll
    for (int off = 16; off; off >>= 1) sm += __shfl_xor_sync(0xffffffffu, sm, off);
    if (lane == 0) red[wp] = sm;
    __syncthreads();
    const float inv = 1.f / (red[0] + red[1]);

    // ---- scaled sparse scatter (rows pre-zeroed by k_h) ----
    {
        unsigned m = row[tid];
        int nb = 0;
        while (m) {
            int b = __ffs(m) - 1;
            m &= m - 1;
            int i = tid * 32 + b;
            float e = (nb < 4) ? evloc[nb] : so[i];      // same-thread re-read, ordered
            so[i] = e * inv;
            if (write_mask) mo[i] = 1.f;
            nb++;
        }
    }
}

// ---------------- launch ----------------
template <typename F, typename... Args>
static void launchPDL(F kern, dim3 g, dim3 b, Args... args) {
    cudaLaunchConfig_t cfg = {};
    cfg.gridDim = g;
    cfg.blockDim = b;
    cfg.dynamicSmemBytes = 0;
    cfg.stream = 0;
    cudaLaunchAttribute at[1];
    at[0].id = cudaLaunchAttributeProgrammaticStreamSerialization;
    at[0].val.programmaticStreamSerializationAllowed = 1;
    cfg.attrs = at;
    cfg.numAttrs = 1;
    cudaLaunchKernelEx(&cfg, kern, args...);
}

extern "C" void kernel_launch(void* const* d_in, const int* in_sizes, int n_in,
                              void* d_out, int out_size) {
    // inputs: 0:x 1:x_orig 2:edge_index 3:batch 4:W2 5:att_src 6:att_dst 7:bias
    const float* x_orig  = (const float*)d_in[1];
    const int*   ei      = (const int*)d_in[2];
    const float* W2      = (const float*)d_in[4];
    const float* att_src = (const float*)d_in[5];
    const float* att_dst = (const float*)d_in[6];
    const float* bias    = (const float*)d_in[7];
    float* out = (float*)d_out;
    int write_mask = (out_size >= 2 * NN * NN) ? 1 : 0;

    k_h<<<1536, 256>>>(x_orig, W2, att_src, att_dst, out, out_size / 4);
    launchPDL(k_scatter, dim3(EE / 256), dim3(256), ei, att_src, att_dst);
    launchPDL(k_ego, dim3(NN), dim3(64), bias, out, write_mask);
}

// round 13
// speedup vs baseline: 1.5366x; 1.5366x over previous
#include <cuda_runtime.h>

#define NN 2048
#define EE 16384
#define DIN 1280
#define MAXDEG 64          // fixed-stride CSR slot capacity
#define EVCAP 1024         // shared e-value cache (fallback: recompute)

// -------- device scratch (no allocation allowed) --------
__device__ float   g_h[NN];               // h = x_orig @ W2^T
__device__ int     g_deg[NN];             // in-degree counters
__device__ float4  g_edge[NN * MAXDEG];   // {src_bits, w, w*h_src, 0} per in-edge of dst
__device__ float2  g_self[NN];            // {self_w, self_w * h_i}

// ------- k_h: h = x_orig @ W2^T, 2 rows/block, 4 warps/row (R8-proven) -------
__global__ void __launch_bounds__(256) k_h(const float* __restrict__ xo,
                    const float* __restrict__ W2,
                    const float* __restrict__ att_src, const float* __restrict__ att_dst) {
    __shared__ float partial[8];
    const int tid = threadIdx.x, wp = tid >> 5, lane = tid & 31;
    const int row = blockIdx.x * 2 + (wp >> 2);
    const int b0 = (wp & 3) * 80;                       // 320 float4 per row / 4 warps
    const float4* xr = (const float4*)(xo + (size_t)row * DIN);
    const float4* wr = (const float4*)W2;

    float acc;
    {
        float4 a = xr[b0 + lane],      b = wr[b0 + lane];
        acc = a.x * b.x + a.y * b.y + a.z * b.z + a.w * b.w;
        a = xr[b0 + 32 + lane];        b = wr[b0 + 32 + lane];
        acc += a.x * b.x + a.y * b.y + a.z * b.z + a.w * b.w;
        if (lane < 16) {
            a = xr[b0 + 64 + lane];    b = wr[b0 + 64 + lane];
            acc += a.x * b.x + a.y * b.y + a.z * b.z + a.w * b.w;
        }
    }
#pragma unroll
    for (int off = 16; off; off >>= 1) acc += __shfl_xor_sync(0xffffffffu, acc, off);
    if (lane == 0) partial[wp] = acc;
    __syncthreads();
    if (tid < 2) {
        int r = blockIdx.x * 2 + tid;
        float h = partial[tid * 4] + partial[tid * 4 + 1]
                + partial[tid * 4 + 2] + partial[tid * 4 + 3];
        g_h[r] = h;
        g_deg[r] = 0;
        float z = (att_src[0] + att_dst[0]) * h;        // self-loop logit
        float self = z > 0.f ? z : 0.2f * z;
        float sw = __expf(self);                         // unshifted (validated)
        g_self[r] = make_float2(sw, sw * h);
    }
}

// ------- k_scatter: CSR scatter + per-edge exp weight (shift-free) -------
__global__ void k_scatter(const int* __restrict__ ei,
                          const float* __restrict__ att_src,
                          const float* __restrict__ att_dst) {
    int e = blockIdx.x * blockDim.x + threadIdx.x;
    if (e < EE) {
        int s = ei[e];
        int d = ei[EE + e];
        float hs = g_h[s], hd = g_h[d];
        float z = att_src[0] * hs + att_dst[0] * hd;
        float l = z > 0.f ? z : 0.2f * z;                // leaky-relu(0.2)
        float w = __expf(l);
        int p = atomicAdd(&g_deg[d], 1);
        if (p < MAXDEG) {
            g_edge[d * MAXDEG + p] = make_float4(__int_as_float(s), w, w * hs, 0.f);
        }
    }
}

// GAT value for node i inside ego mask `row`
__device__ __forceinline__ float ego_e(int i, const unsigned* row, float bi) {
    float2 sf = g_self[i];
    float denom = sf.x, num = sf.y;
    int di = min(g_deg[i], MAXDEG);
    const float4* ep = g_edge + i * MAXDEG;
#pragma unroll 4
    for (int j = 0; j < di; j++) {
        float4 pk = ep[j];
        int s = __float_as_int(pk.x);
        if ((row[s >> 5] >> (s & 31)) & 1u) { denom += pk.y; num += pk.z; }
    }
    return __expf(num / denom + bi);
}

// ------- k_ego: block/ego (256 thr) — zero rows FIRST, mask, GAT+softmax, scatter -------
__global__ void __launch_bounds__(256) k_ego(const float* __restrict__ bias,
                                             float* __restrict__ out, int write_mask) {
    __shared__ unsigned row[64];
    __shared__ unsigned short list[NN];
    __shared__ float ev[EVCAP];
    __shared__ int s1[MAXDEG];
    __shared__ int s1d[MAXDEG];
    __shared__ int woff[64];
    __shared__ float red[8];
    const int v = blockIdx.x;
    const int tid = threadIdx.x, lane = tid & 31, wp = tid >> 5;
    const float bi = bias[0];

    float* so = out + (size_t)v * NN;
    float* mo = out + (size_t)NN * NN + (size_t)v * NN;

    // ---- 0: zero this ego's output rows FIRST (stores drain under later loads) ----
    {
        float4 z4 = make_float4(0.f, 0.f, 0.f, 0.f);
        float4* so4 = (float4*)so;
        float4* mo4 = (float4*)mo;
#pragma unroll
        for (int t = tid; t < NN / 4; t += 256) {
            so4[t] = z4;
            if (write_mask) mo4[t] = z4;
        }
    }
    if (tid < 64) row[tid] = 0u;
    __syncthreads();

    // ---- 1: 1-hop into shared ----
    const int dv = min(g_deg[v], MAXDEG);
    if (tid == 0) atomicOr(&row[v >> 5], 1u << (v & 31));
    const float* ex = (const float*)g_edge;              // .x at stride 4
    for (int k = tid; k < dv; k += 256) {
        int s = __float_as_int(__ldg(&ex[(v * MAXDEG + k) * 4]));
        s1[k] = s;
        s1d[k] = min(g_deg[s], MAXDEG);
        atomicOr(&row[s >> 5], 1u << (s & 31));
    }
    __syncthreads();

    // ---- 2: 2-hop, flat (k, j) parallel — all loads independent ----
    const int tot = dv * MAXDEG;
    for (int t = tid; t < tot; t += 256) {
        int k = t >> 6, j = t & 63;
        if (j < s1d[k]) {
            int s = s1[k];
            int u = __float_as_int(__ldg(&ex[(s * MAXDEG + j) * 4]));
            atomicOr(&row[u >> 5], 1u << (u & 31));
        }
    }
    __syncthreads();

    // ---- 3: compact node ids via popc + shfl prefix scan ----
    if (tid < 64) {
        int sc = __popc(row[tid]);
#pragma unroll
        for (int o = 1; o < 32; o <<= 1) {
            int t2 = __shfl_up_sync(0xffffffffu, sc, o);
            if (lane >= o) sc += t2;
        }
        woff[tid] = sc;                                  // inclusive within each warp
    }
    __syncthreads();
    const int base0 = woff[31];
    const int n = woff[63] + base0;
    if (tid < 64) {
        unsigned m = row[tid];
        int p = ((tid < 32) ? woff[tid] : woff[tid] + base0) - __popc(m);
        while (m) {
            int b = __ffs(m) - 1;
            m &= m - 1;
            list[p++] = (unsigned short)(tid * 32 + b);
        }
    }
    __syncthreads();

    // ---- 4: GAT + exp per ego node, block sum ----
    float sm = 0.f;
    for (int idx = tid; idx < n; idx += 256) {
        float e = ego_e(list[idx], row, bi);
        if (idx < EVCAP) ev[idx] = e;
        sm += e;
    }
#pragma unroll
    for (int off = 16; off; off >>= 1) sm += __shfl_xor_sync(0xffffffffu, sm, off);
    if (lane == 0) red[wp] = sm;
    __syncthreads();                                     // orders zero-stores too
    const float inv = 1.f / (red[0] + red[1] + red[2] + red[3]
                           + red[4] + red[5] + red[6] + red[7]);

    // ---- 5: sparse scatter of the ~n nonzeros ----
    for (int idx = tid; idx < n; idx += 256) {
        int i = list[idx];
        float e = (idx < EVCAP) ? ev[idx] : ego_e(i, row, bi);
        so[i] = e * inv;
        if (write_mask) mo[i] = 1.f;
    }
}

// ---------------- launch ----------------
extern "C" void kernel_launch(void* const* d_in, const int* in_sizes, int n_in,
                              void* d_out, int out_size) {
    // inputs: 0:x 1:x_orig 2:edge_index 3:batch 4:W2 5:att_src 6:att_dst 7:bias
    const float* x_orig  = (const float*)d_in[1];
    const int*   ei      = (const int*)d_in[2];
    const float* W2      = (const float*)d_in[4];
    const float* att_src = (const float*)d_in[5];
    const float* att_dst = (const float*)d_in[6];
    const float* bias    = (const float*)d_in[7];
    float* out = (float*)d_out;
    int write_mask = (out_size >= 2 * NN * NN) ? 1 : 0;

    k_h<<<NN / 2, 256>>>(x_orig, W2, att_src, att_dst);  // 4 warps/row
    k_scatter<<<EE / 256, 256>>>(ei, att_src, att_dst);
    k_ego<<<NN, 256>>>(bias, out, write_mask);
}